// round 1
// baseline (speedup 1.0000x reference)
#include <cuda_runtime.h>

#define NPIX 9216          // 96*96
#define DIM  32
#define ISPLIT 4
#define ICHUNK (NPIX/ISPLIT)   // 2304
#define TI   64
#define JBLK 256
#define FELEMS (DIM*NPIX)      // 294912

// scratch (no allocations allowed -> device globals)
__device__ float g_xbuf0[FELEMS];
__device__ float g_xbuf1[FELEMS];
__device__ float g_pv[ISPLIT*DIM*NPIX];   // partial v, layout [ib][d][j]
__device__ float g_ps[ISPLIT*NPIX];       // partial s, layout [ib][j]

__device__ __forceinline__ unsigned long long pack2(float lo, float hi) {
    unsigned long long r;
    asm("mov.b64 %0, {%1,%2};" : "=l"(r) : "f"(lo), "f"(hi));
    return r;
}
__device__ __forceinline__ void unpack2(unsigned long long v, float& lo, float& hi) {
    asm("mov.b64 {%0,%1}, %2;" : "=f"(lo), "=f"(hi) : "l"(v));
}
#define FMA2(d_, a_, b_, c_) \
    asm("fma.rn.f32x2 %0, %1, %2, %3;" : "=l"(d_) : "l"(a_), "l"(b_), "l"(c_))
#define ADD2(d_, a_, b_) \
    asm("add.rn.f32x2 %0, %1, %2;" : "=l"(d_) : "l"(a_), "l"(b_))

// Fused pass: for j in this block, over i in [i0, i0+ICHUNK):
//   s_j += exp(3*<x_i, x_j>) ; v_j += x_i * exp(3*<x_i, x_j>)
// Packed f32x2 along the i dimension (2 i's per instruction).
__global__ void __launch_bounds__(JBLK) kernel_main(const float* __restrict__ xext, int sel)
{
    const float* __restrict__ X = (sel == 0) ? xext : (sel == 1 ? g_xbuf0 : g_xbuf1);

    __shared__ __align__(16) float xs[DIM][TI];

    const int tid = threadIdx.x;
    const int j   = blockIdx.x * JBLK + tid;
    const int i0  = blockIdx.y * ICHUNK;

    // query column j, each value duplicated into both f32x2 lanes
    unsigned long long xqp[DIM];
#pragma unroll
    for (int d = 0; d < DIM; d++) {
        float q = X[d * NPIX + j];
        xqp[d] = pack2(q, q);
    }

    unsigned long long vp[DIM];
#pragma unroll
    for (int d = 0; d < DIM; d++) vp[d] = 0ull;   // (0.0f, 0.0f)
    unsigned long long sp = 0ull;

    for (int it = 0; it < ICHUNK; it += TI) {
        __syncthreads();
        // cooperative tile load: 32x64 floats, coalesced, conflict-free
#pragma unroll
        for (int k = 0; k < (DIM * TI) / JBLK; k++) {
            int sI = tid + k * JBLK;
            int d  = sI >> 6;
            int ti = sI & 63;
            xs[d][ti] = X[d * NPIX + i0 + it + ti];
        }
        __syncthreads();

#pragma unroll 2
        for (int ii = 0; ii < TI; ii += 2) {
            // --- dot pass: (dot_i0, dot_i1), 4 independent accumulators ---
            unsigned long long a0 = 0ull, a1 = 0ull, a2 = 0ull, a3 = 0ull;
#pragma unroll
            for (int d = 0; d < DIM; d += 4) {
                unsigned long long x0 = *(const unsigned long long*)&xs[d + 0][ii];
                unsigned long long x1 = *(const unsigned long long*)&xs[d + 1][ii];
                unsigned long long x2 = *(const unsigned long long*)&xs[d + 2][ii];
                unsigned long long x3 = *(const unsigned long long*)&xs[d + 3][ii];
                FMA2(a0, xqp[d + 0], x0, a0);
                FMA2(a1, xqp[d + 1], x1, a1);
                FMA2(a2, xqp[d + 2], x2, a2);
                FMA2(a3, xqp[d + 3], x3, a3);
            }
            ADD2(a0, a0, a1);
            ADD2(a2, a2, a3);
            ADD2(a0, a0, a2);
            float dt0, dt1;
            unpack2(a0, dt0, dt1);
            float w0 = __expf(3.0f * dt0);
            float w1 = __expf(3.0f * dt1);
            unsigned long long w2 = pack2(w0, w1);
            ADD2(sp, sp, w2);
            // --- accumulate v: vp[d] += (w0,w1) * (xs[d][i0], xs[d][i1]) ---
#pragma unroll
            for (int d = 0; d < DIM; d++) {
                unsigned long long xv = *(const unsigned long long*)&xs[d][ii];
                FMA2(vp[d], w2, xv, vp[d]);
            }
        }
    }

    // write partials
    float s0, s1;
    unpack2(sp, s0, s1);
    g_ps[blockIdx.y * NPIX + j] = s0 + s1;
#pragma unroll
    for (int d = 0; d < DIM; d++) {
        float lo, hi;
        unpack2(vp[d], lo, hi);
        g_pv[(blockIdx.y * DIM + d) * NPIX + j] = lo + hi;
    }
}

// Combine ISPLIT partials, apply update, write x_new + output slot(s).
__global__ void kernel_reduce(const float* __restrict__ xext, int sel_src, int sel_dst,
                              float* __restrict__ out, int stack_off, int final_off)
{
    int idx = blockIdx.x * blockDim.x + threadIdx.x;
    if (idx >= FELEMS) return;
    int d = idx / NPIX;
    int j = idx - d * NPIX;

    const float* __restrict__ xold = (sel_src == 0) ? xext : (sel_src == 1 ? g_xbuf0 : g_xbuf1);
    float* __restrict__ xnew = (sel_dst == 1) ? g_xbuf0 : g_xbuf1;

    float s = 0.0f, v = 0.0f;
#pragma unroll
    for (int ib = 0; ib < ISPLIT; ib++) {
        s += g_ps[ib * NPIX + j];
        v += g_pv[(ib * DIM + d) * NPIX + j];
    }
    float val = 0.5f * v / s + 0.5f * xold[idx];
    xnew[idx] = val;
    out[stack_off + idx] = val;
    if (final_off >= 0) out[final_off + idx] = val;
}

extern "C" void kernel_launch(void* const* d_in, const int* in_sizes, int n_in,
                              void* d_out, int out_size)
{
    const float* x = (const float*)d_in[0];
    float* out = (float*)d_out;

    dim3 grid_main(NPIX / JBLK, ISPLIT);     // (36, 4) = 144 blocks, one wave
    const int rgrid = (FELEMS + 255) / 256;  // 1152

    // iter 0: src = input, dst = buf0
    kernel_main<<<grid_main, JBLK>>>(x, 0);
    kernel_reduce<<<rgrid, 256>>>(x, 0, 1, out, FELEMS + 0 * FELEMS, -1);
    // iter 1: src = buf0, dst = buf1
    kernel_main<<<grid_main, JBLK>>>(x, 1);
    kernel_reduce<<<rgrid, 256>>>(x, 1, 2, out, FELEMS + 1 * FELEMS, -1);
    // iter 2: src = buf1, dst = buf0; also write final at offset 0
    kernel_main<<<grid_main, JBLK>>>(x, 2);
    kernel_reduce<<<rgrid, 256>>>(x, 2, 1, out, FELEMS + 2 * FELEMS, 0);
}

// round 3
// speedup vs baseline: 4.8382x; 4.8382x over previous
#include <cuda_runtime.h>
#include <cuda_bf16.h>
#include <stdint.h>

#define NPIX 9216
#define DIMK 32
#define FELEMS (DIMK*NPIX)
#define JT 128
#define TI 64
#define ISPLIT 4
#define IRANGE (NPIX/ISPLIT)   // 2304
#define NCH (IRANGE/TI)        // 36
#define SCALE 4.328085122666891f   // 3 * log2(e)

// device scratch (no allocations allowed)
__device__ __nv_bfloat16 g_xq[NPIX*DIMK];   // [pixel][d], scaled by 3*log2e (A1 operand)
__device__ __nv_bfloat16 g_xp[NPIX*DIMK];   // [pixel][d], unscaled (B1 operand)
__device__ __nv_bfloat16 g_xa[DIMK*NPIX];   // [d][pixel], unscaled (B2 operand)
__device__ float g_xf[FELEMS];              // current x fp32, d-major
__device__ float g_pv[ISPLIT*FELEMS];       // partial v [split][d][j]
__device__ float g_ps[ISPLIT*NPIX];         // partial s [split][j]

__device__ __forceinline__ uint32_t smem_u32(const void* p) {
    uint32_t a;
    asm("{ .reg .u64 t; cvta.to.shared.u64 t, %1; cvt.u32.u64 %0, t; }" : "=r"(a) : "l"(p));
    return a;
}

#define LDSM4(r0,r1,r2,r3,addr) \
    asm volatile("ldmatrix.sync.aligned.m8n8.x4.shared.b16 {%0,%1,%2,%3}, [%4];" \
        : "=r"(r0),"=r"(r1),"=r"(r2),"=r"(r3) : "r"(addr))

#define MMA16816(C, A, b0, b1) \
    asm volatile("mma.sync.aligned.m16n8k16.row.col.f32.bf16.bf16.f32 " \
        "{%0,%1,%2,%3}, {%4,%5,%6,%7}, {%8,%9}, {%0,%1,%2,%3};" \
        : "+f"((C)[0]), "+f"((C)[1]), "+f"((C)[2]), "+f"((C)[3]) \
        : "r"((A)[0]), "r"((A)[1]), "r"((A)[2]), "r"((A)[3]), "r"(b0), "r"(b1))

__device__ __forceinline__ void cp16(uint32_t dst, const void* src) {
    asm volatile("cp.async.ca.shared.global [%0], [%1], 16;"
        :: "r"(dst), "l"(__cvta_generic_to_global(src)) : "memory");
}
__device__ __forceinline__ float ex2f(float x) {
    float r; asm("ex2.approx.f32 %0, %1;" : "=f"(r) : "f"(x)); return r;
}
__device__ __forceinline__ uint32_t packbf2(float lo, float hi) {
    uint32_t r; asm("cvt.rn.bf16x2.f32 %0, %1, %2;" : "=r"(r) : "f"(hi), "f"(lo)); return r;
}

// smem: sXi = 2 bufs x (64 rows x 80B)  [i][d] pad-80  -> 10240 B
//       sXd = 2 bufs x (32 rows x 144B) [d][i] pad-144 ->  9216 B
#define SXI_STRIDE 80
#define SXD_STRIDE 144
#define SXI_BUF (TI*SXI_STRIDE)       // 5120
#define SXD_BUF (DIMK*SXD_STRIDE)    // 4608
#define SMEM_BYTES (2*SXI_BUF + 2*SXD_BUF)

__global__ void __launch_bounds__(256, 2) ms_main()
{
    __shared__ __align__(128) unsigned char smem_buf[SMEM_BYTES];
    const uint32_t sXi = smem_u32(smem_buf);
    const uint32_t sXd = sXi + 2 * SXI_BUF;

    const int tid = threadIdx.x;
    const int w = tid >> 5;
    const int l = tid & 31;
    const int jb = blockIdx.x * JT;
    const int split = blockIdx.y;
    const int i0b = split * IRANGE;

    // A1 fragments: Xq rows (jb + w*16 ..), loaded once, direct from gmem
    const uint32_t* xq32 = (const uint32_t*)g_xq;
    const int row0 = jb + w * 16 + (l >> 2);
    uint32_t a1f[2][4];
#pragma unroll
    for (int ks = 0; ks < 2; ks++) {
        a1f[ks][0] = xq32[row0 * 16 + ks * 8 + (l & 3)];
        a1f[ks][1] = xq32[(row0 + 8) * 16 + ks * 8 + (l & 3)];
        a1f[ks][2] = xq32[row0 * 16 + ks * 8 + 4 + (l & 3)];
        a1f[ks][3] = xq32[(row0 + 8) * 16 + ks * 8 + 4 + (l & 3)];
    }

    float vf[4][4];
#pragma unroll
    for (int n = 0; n < 4; n++)
#pragma unroll
        for (int q = 0; q < 4; q++) vf[n][q] = 0.0f;
    float s0 = 0.0f, s1 = 0.0f;

    const char* gxp = (const char*)g_xp;
    const char* gxa = (const char*)g_xa;

    // async-load chunk c into buffer c&1
    const int xi_r = tid >> 2, xi_c = tid & 3;   // 64 rows x 4 chunks
    const int xd_r = tid >> 3, xd_c = tid & 7;   // 32 rows x 8 chunks

#define ISSUE(c) do { \
        int i0_ = i0b + (c) * TI; int b_ = (c) & 1; \
        cp16(sXi + b_ * SXI_BUF + xi_r * SXI_STRIDE + xi_c * 16, \
             gxp + (size_t)(i0_ + xi_r) * 64 + xi_c * 16); \
        cp16(sXd + b_ * SXD_BUF + xd_r * SXD_STRIDE + xd_c * 16, \
             gxa + ((size_t)xd_r * NPIX + i0_) * 2 + xd_c * 16); \
        asm volatile("cp.async.commit_group;" ::: "memory"); \
    } while (0)

    ISSUE(0);

    for (int c = 0; c < NCH; c++) {
        if (c + 1 < NCH) {
            ISSUE(c + 1);
            asm volatile("cp.async.wait_group 1;" ::: "memory");
        } else {
            asm volatile("cp.async.wait_group 0;" ::: "memory");
        }
        __syncthreads();

        const uint32_t pXi = sXi + (c & 1) * SXI_BUF;
        const uint32_t pXd = sXd + (c & 1) * SXD_BUF;

        // ---- MMA1: S[j(16), i(64)] ----
        float C[8][4];
#pragma unroll
        for (int n = 0; n < 8; n++) {
            uint32_t q0, q1, q2, q3;
            uint32_t addr = pXi + (n * 8 + (l & 7)) * SXI_STRIDE + (l >> 3) * 16;
            LDSM4(q0, q1, q2, q3, addr);
            C[n][0] = 0.f; C[n][1] = 0.f; C[n][2] = 0.f; C[n][3] = 0.f;
            MMA16816(C[n], a1f[0], q0, q1);
            MMA16816(C[n], a1f[1], q2, q3);
        }

        // ---- exp + rowsum + pack to A2 fragments ----
        uint32_t a2f[4][4];
#pragma unroll
        for (int n = 0; n < 8; n++) {
            float e0 = ex2f(C[n][0]);
            float e1 = ex2f(C[n][1]);
            float e2 = ex2f(C[n][2]);
            float e3 = ex2f(C[n][3]);
            s0 += e0 + e1;
            s1 += e2 + e3;
            int kk = n >> 1;
            if ((n & 1) == 0) {
                a2f[kk][0] = packbf2(e0, e1);
                a2f[kk][1] = packbf2(e2, e3);
            } else {
                a2f[kk][2] = packbf2(e0, e1);
                a2f[kk][3] = packbf2(e2, e3);
            }
        }

        // ---- MMA2: V[j(16), d(32)] += P * Xd ----
#pragma unroll
        for (int nd = 0; nd < 4; nd++) {
#pragma unroll
            for (int p = 0; p < 2; p++) {
                uint32_t q0, q1, q2, q3;
                uint32_t addr = pXd + (nd * 8 + (l & 7)) * SXD_STRIDE + p * 64 + (l >> 3) * 16;
                LDSM4(q0, q1, q2, q3, addr);
                MMA16816(vf[nd], a2f[2 * p], q0, q1);
                MMA16816(vf[nd], a2f[2 * p + 1], q2, q3);
            }
        }
        __syncthreads();
    }

    // ---- s rowsum reduce within quads ----
    s0 += __shfl_xor_sync(0xFFFFFFFF, s0, 1);
    s0 += __shfl_xor_sync(0xFFFFFFFF, s0, 2);
    s1 += __shfl_xor_sync(0xFFFFFFFF, s1, 1);
    s1 += __shfl_xor_sync(0xFFFFFFFF, s1, 2);
    if ((l & 3) == 0) {
        g_ps[split * NPIX + jb + w * 16 + (l >> 2)] = s0;
        g_ps[split * NPIX + jb + w * 16 + (l >> 2) + 8] = s1;
    }

    // ---- V writeback ----
#pragma unroll
    for (int nd = 0; nd < 4; nd++) {
#pragma unroll
        for (int q = 0; q < 4; q++) {
            int d = nd * 8 + (l & 3) * 2 + (q & 1);
            int j = jb + w * 16 + (l >> 2) + ((q >= 2) ? 8 : 0);
            g_pv[(split * DIMK + d) * NPIX + j] = vf[nd][q];
        }
    }
}

// fp32 input -> the three bf16 layouts
__global__ void ms_prep(const float* __restrict__ x)
{
    int j = blockIdx.x * 256 + threadIdx.x;
    float v[DIMK];
#pragma unroll
    for (int d = 0; d < DIMK; d++) {
        v[d] = x[d * NPIX + j];
        g_xa[d * NPIX + j] = __float2bfloat16(v[d]);
    }
    uint32_t* xp32 = (uint32_t*)g_xp;
    uint32_t* xq32 = (uint32_t*)g_xq;
#pragma unroll
    for (int d = 0; d < DIMK; d += 2) {
        __nv_bfloat162 p = __floats2bfloat162_rn(v[d], v[d + 1]);
        xp32[j * 16 + d / 2] = *(uint32_t*)&p;
        __nv_bfloat162 q = __floats2bfloat162_rn(v[d] * SCALE, v[d + 1] * SCALE);
        xq32[j * 16 + d / 2] = *(uint32_t*)&q;
    }
}

// combine partials, apply update, refresh layouts, write outputs
__global__ void ms_reduce(const float* __restrict__ xext, int use_ext,
                          float* __restrict__ out, int stack_off, int final_off)
{
    int j = blockIdx.x * 256 + threadIdx.x;
    float s = 0.0f;
#pragma unroll
    for (int ib = 0; ib < ISPLIT; ib++) s += g_ps[ib * NPIX + j];
    float inv = 0.5f / s;
    float v[DIMK];
#pragma unroll
    for (int d = 0; d < DIMK; d++) {
        float pv = 0.0f;
#pragma unroll
        for (int ib = 0; ib < ISPLIT; ib++) pv += g_pv[(ib * DIMK + d) * NPIX + j];
        float xo = use_ext ? xext[d * NPIX + j] : g_xf[d * NPIX + j];
        float val = pv * inv + 0.5f * xo;
        v[d] = val;
        out[stack_off + d * NPIX + j] = val;
        if (final_off >= 0) out[final_off + d * NPIX + j] = val;
        g_xf[d * NPIX + j] = val;
        g_xa[d * NPIX + j] = __float2bfloat16(val);
    }
    uint32_t* xp32 = (uint32_t*)g_xp;
    uint32_t* xq32 = (uint32_t*)g_xq;
#pragma unroll
    for (int d = 0; d < DIMK; d += 2) {
        __nv_bfloat162 p = __floats2bfloat162_rn(v[d], v[d + 1]);
        xp32[j * 16 + d / 2] = *(uint32_t*)&p;
        __nv_bfloat162 q = __floats2bfloat162_rn(v[d] * SCALE, v[d + 1] * SCALE);
        xq32[j * 16 + d / 2] = *(uint32_t*)&q;
    }
}

extern "C" void kernel_launch(void* const* d_in, const int* in_sizes, int n_in,
                              void* d_out, int out_size)
{
    const float* x = (const float*)d_in[0];
    float* out = (float*)d_out;

    dim3 grid_main(NPIX / JT, ISPLIT);   // (72, 4) = 288 CTAs, 2 per SM

    ms_prep<<<NPIX / 256, 256>>>(x);
    for (int it = 0; it < 3; it++) {
        ms_main<<<grid_main, 256>>>();
        ms_reduce<<<NPIX / 256, 256>>>(x, it == 0 ? 1 : 0, out,
                                       FELEMS * (1 + it), it == 2 ? 0 : -1);
    }
}

// round 4
// speedup vs baseline: 4.8673x; 1.0060x over previous
#include <cuda_runtime.h>
#include <cuda_fp16.h>
#include <stdint.h>

#define NPIX 9216
#define DIMK 32
#define FELEMS (DIMK*NPIX)
#define JT 128
#define TI 64
#define ISPLIT 6
#define IRANGE (NPIX/ISPLIT)   // 1536
#define NCH (IRANGE/TI)        // 24
#define SCALE 4.328085122666891f   // 3 * log2(e)

// device scratch (no allocations allowed)
__device__ __half g_xq[NPIX*DIMK];   // [pixel][d], scaled by 3*log2e (A1 operand)
__device__ __half g_xp[NPIX*DIMK];   // [pixel][d], unscaled (B1 operand)
__device__ __half g_xa[DIMK*NPIX];   // [d][pixel], unscaled (B2 operand)
__device__ float g_xf[FELEMS];       // current x fp32, d-major
__device__ float g_pv[ISPLIT*FELEMS];  // partial v [split][d][j]
__device__ float g_ps[ISPLIT*NPIX];    // partial s [split][j]

__device__ __forceinline__ uint32_t smem_u32(const void* p) {
    uint32_t a;
    asm("{ .reg .u64 t; cvta.to.shared.u64 t, %1; cvt.u32.u64 %0, t; }" : "=r"(a) : "l"(p));
    return a;
}

#define LDSM4(r0,r1,r2,r3,addr) \
    asm volatile("ldmatrix.sync.aligned.m8n8.x4.shared.b16 {%0,%1,%2,%3}, [%4];" \
        : "=r"(r0),"=r"(r1),"=r"(r2),"=r"(r3) : "r"(addr))

#define MMA16816(C, A, b0, b1) \
    asm volatile("mma.sync.aligned.m16n8k16.row.col.f32.f16.f16.f32 " \
        "{%0,%1,%2,%3}, {%4,%5,%6,%7}, {%8,%9}, {%0,%1,%2,%3};" \
        : "+f"((C)[0]), "+f"((C)[1]), "+f"((C)[2]), "+f"((C)[3]) \
        : "r"((A)[0]), "r"((A)[1]), "r"((A)[2]), "r"((A)[3]), "r"(b0), "r"(b1))

__device__ __forceinline__ void cp16(uint32_t dst, const void* src) {
    asm volatile("cp.async.ca.shared.global [%0], [%1], 16;"
        :: "r"(dst), "l"(__cvta_generic_to_global(src)) : "memory");
}
// pack two fp32 into f16x2 (lo, hi)
__device__ __forceinline__ uint32_t pkh2(float lo, float hi) {
    uint32_t r; asm("cvt.rn.f16x2.f32 %0, %1, %2;" : "=r"(r) : "f"(hi), "f"(lo)); return r;
}
__device__ __forceinline__ uint32_t ex2h2(uint32_t x) {
    uint32_t r; asm("ex2.approx.f16x2 %0, %1;" : "=r"(r) : "r"(x)); return r;
}

// smem layout:
//   sXi: 2 bufs x (64 rows x 80B)   [i][d]     -> 10240 B
//   sXd: 2 bufs x (40 rows x 144B)  [d(+ones)][i] -> 11520 B
#define SXI_STRIDE 80
#define SXD_STRIDE 144
#define SXI_BUF (TI*SXI_STRIDE)      // 5120
#define SXD_BUF (40*SXD_STRIDE)      // 5760
#define SMEM_BYTES (2*SXI_BUF + 2*SXD_BUF)

__global__ void __launch_bounds__(256, 3) ms_main()
{
    __shared__ __align__(128) unsigned char smem_buf[SMEM_BYTES];
    const uint32_t sXi = smem_u32(smem_buf);
    const uint32_t sXd = sXi + 2 * SXI_BUF;

    const int tid = threadIdx.x;
    const int w = tid >> 5;
    const int l = tid & 31;
    const int jb = blockIdx.x * JT;
    const int split = blockIdx.y;
    const int i0b = split * IRANGE;

    // init the extra Xd rows: row 32 = ones (s column), rows 33..39 = zeros
    // 2 bufs x 8 rows x 32 u32 = 512 words
    for (int idx = tid; idx < 512; idx += 256) {
        int b = idx >> 8, rem = idx & 255;
        int r = rem >> 5, cw = rem & 31;
        uint32_t v = (r == 0) ? 0x3C003C00u : 0u;
        *(uint32_t*)(smem_buf + 2 * SXI_BUF + b * SXD_BUF + (32 + r) * SXD_STRIDE + cw * 4) = v;
    }

    // A1 fragments: Xq rows (jb + w*16 ..), loaded once, direct from gmem
    const uint32_t* xq32 = (const uint32_t*)g_xq;
    const int row0 = jb + w * 16 + (l >> 2);
    uint32_t a1f[2][4];
#pragma unroll
    for (int ks = 0; ks < 2; ks++) {
        a1f[ks][0] = xq32[row0 * 16 + ks * 8 + (l & 3)];
        a1f[ks][1] = xq32[(row0 + 8) * 16 + ks * 8 + (l & 3)];
        a1f[ks][2] = xq32[row0 * 16 + ks * 8 + 4 + (l & 3)];
        a1f[ks][3] = xq32[(row0 + 8) * 16 + ks * 8 + 4 + (l & 3)];
    }

    float vf[5][4];
#pragma unroll
    for (int n = 0; n < 5; n++)
#pragma unroll
        for (int q = 0; q < 4; q++) vf[n][q] = 0.0f;

    const char* gxp = (const char*)g_xp;
    const char* gxa = (const char*)g_xa;

    const int xi_r = tid >> 2, xi_c = tid & 3;   // 64 rows x 4 x 16B
    const int xd_r = tid >> 3, xd_c = tid & 7;   // 32 rows x 8 x 16B

#define ISSUE(c) do { \
        int i0_ = i0b + (c) * TI; int b_ = (c) & 1; \
        cp16(sXi + b_ * SXI_BUF + xi_r * SXI_STRIDE + xi_c * 16, \
             gxp + (size_t)(i0_ + xi_r) * 64 + xi_c * 16); \
        cp16(sXd + b_ * SXD_BUF + xd_r * SXD_STRIDE + xd_c * 16, \
             gxa + ((size_t)xd_r * NPIX + i0_) * 2 + xd_c * 16); \
        asm volatile("cp.async.commit_group;" ::: "memory"); \
    } while (0)

    ISSUE(0);

    for (int c = 0; c < NCH; c++) {
        if (c + 1 < NCH) {
            ISSUE(c + 1);
            asm volatile("cp.async.wait_group 1;" ::: "memory");
        } else {
            asm volatile("cp.async.wait_group 0;" ::: "memory");
        }
        __syncthreads();

        const uint32_t pXi = sXi + (c & 1) * SXI_BUF;
        const uint32_t pXd = sXd + (c & 1) * SXD_BUF;

        // ---- MMA1 + exp, one n-block (j16 x i8) at a time ----
        uint32_t a2f[4][4];
#pragma unroll
        for (int n = 0; n < 8; n++) {
            uint32_t q0, q1, q2, q3;
            uint32_t addr = pXi + (n * 8 + (l & 7)) * SXI_STRIDE + (l >> 3) * 16;
            LDSM4(q0, q1, q2, q3, addr);
            float C[4];
            C[0] = 0.f; C[1] = 0.f; C[2] = 0.f; C[3] = 0.f;
            MMA16816(C, a1f[0], q0, q1);
            MMA16816(C, a1f[1], q2, q3);
            // packed exp (already in log2 domain via scaled A1)
            uint32_t e01 = ex2h2(pkh2(C[0], C[1]));
            uint32_t e23 = ex2h2(pkh2(C[2], C[3]));
            int kk = n >> 1;
            if ((n & 1) == 0) { a2f[kk][0] = e01; a2f[kk][1] = e23; }
            else             { a2f[kk][2] = e01; a2f[kk][3] = e23; }
        }

        // ---- MMA2: V[j(16), d(40)] += P * Xd  (col 32 = rowsum via ones) ----
#pragma unroll
        for (int nd = 0; nd < 5; nd++) {
#pragma unroll
            for (int p = 0; p < 2; p++) {
                uint32_t q0, q1, q2, q3;
                uint32_t addr = pXd + (nd * 8 + (l & 7)) * SXD_STRIDE + p * 64 + (l >> 3) * 16;
                LDSM4(q0, q1, q2, q3, addr);
                MMA16816(vf[nd], a2f[2 * p], q0, q1);
                MMA16816(vf[nd], a2f[2 * p + 1], q2, q3);
            }
        }
        __syncthreads();
    }

    // ---- s from ones-column (col 32 => nd=4, (l&3)==0, q in {0,2}) ----
    if ((l & 3) == 0) {
        int j0 = jb + w * 16 + (l >> 2);
        g_ps[split * NPIX + j0] = vf[4][0];
        g_ps[split * NPIX + j0 + 8] = vf[4][2];
    }

    // ---- V writeback ----
#pragma unroll
    for (int nd = 0; nd < 4; nd++) {
#pragma unroll
        for (int q = 0; q < 4; q++) {
            int d = nd * 8 + (l & 3) * 2 + (q & 1);
            int j = jb + w * 16 + (l >> 2) + ((q >= 2) ? 8 : 0);
            g_pv[(split * DIMK + d) * NPIX + j] = vf[nd][q];
        }
    }
}

// fp32 input -> the three f16 layouts
__global__ void ms_prep(const float* __restrict__ x)
{
    int j = blockIdx.x * 256 + threadIdx.x;
    float v[DIMK];
#pragma unroll
    for (int d = 0; d < DIMK; d++) {
        v[d] = x[d * NPIX + j];
        g_xa[d * NPIX + j] = __float2half_rn(v[d]);
    }
    uint32_t* xp32 = (uint32_t*)g_xp;
    uint32_t* xq32 = (uint32_t*)g_xq;
#pragma unroll
    for (int d = 0; d < DIMK; d += 2) {
        xp32[j * 16 + d / 2] = pkh2(v[d], v[d + 1]);
        xq32[j * 16 + d / 2] = pkh2(v[d] * SCALE, v[d + 1] * SCALE);
    }
}

// combine partials, apply update, refresh layouts, write outputs
__global__ void ms_reduce(const float* __restrict__ xext, int use_ext,
                          float* __restrict__ out, int stack_off, int final_off)
{
    int j = blockIdx.x * 256 + threadIdx.x;
    float s = 0.0f;
#pragma unroll
    for (int ib = 0; ib < ISPLIT; ib++) s += g_ps[ib * NPIX + j];
    float inv = 0.5f / s;
    float v[DIMK];
#pragma unroll
    for (int d = 0; d < DIMK; d++) {
        float pv = 0.0f;
#pragma unroll
        for (int ib = 0; ib < ISPLIT; ib++) pv += g_pv[(ib * DIMK + d) * NPIX + j];
        float xo = use_ext ? xext[d * NPIX + j] : g_xf[d * NPIX + j];
        float val = pv * inv + 0.5f * xo;
        v[d] = val;
        out[stack_off + d * NPIX + j] = val;
        if (final_off >= 0) out[final_off + d * NPIX + j] = val;
        g_xf[d * NPIX + j] = val;
        g_xa[d * NPIX + j] = __float2half_rn(val);
    }
    uint32_t* xp32 = (uint32_t*)g_xp;
    uint32_t* xq32 = (uint32_t*)g_xq;
#pragma unroll
    for (int d = 0; d < DIMK; d += 2) {
        xp32[j * 16 + d / 2] = pkh2(v[d], v[d + 1]);
        xq32[j * 16 + d / 2] = pkh2(v[d] * SCALE, v[d + 1] * SCALE);
    }
}

extern "C" void kernel_launch(void* const* d_in, const int* in_sizes, int n_in,
                              void* d_out, int out_size)
{
    const float* x = (const float*)d_in[0];
    float* out = (float*)d_out;

    dim3 grid_main(NPIX / JT, ISPLIT);   // (72, 6) = 432 CTAs, ~3 per SM

    ms_prep<<<NPIX / 256, 256>>>(x);
    for (int it = 0; it < 3; it++) {
        ms_main<<<grid_main, 256>>>();
        ms_reduce<<<NPIX / 256, 256>>>(x, it == 0 ? 1 : 0, out,
                                       FELEMS * (1 + it), it == 2 ? 0 : -1);
    }
}

// round 5
// speedup vs baseline: 5.1768x; 1.0636x over previous
#include <cuda_runtime.h>
#include <cuda_fp16.h>
#include <stdint.h>

#define NPIX 9216
#define DIMK 32
#define FELEMS (DIMK*NPIX)
#define JT 256
#define TI 64
#define ISPLIT 8
#define IRANGE (NPIX/ISPLIT)   // 1152
#define NCH (IRANGE/TI)        // 18
#define SCALE 4.328085122666891f   // 3 * log2(e)

// device scratch (no allocations allowed)
__device__ __half g_xq[NPIX*DIMK];   // [pixel][d], scaled by 3*log2e (A1 operand)
__device__ __half g_xp[NPIX*DIMK];   // [pixel][d], unscaled (B1 operand)
__device__ __half g_xa[DIMK*NPIX];   // [d][pixel], unscaled (B2 operand)
__device__ float g_xf[FELEMS];       // current x fp32, d-major
__device__ float g_pv[ISPLIT*FELEMS];  // partial v [split][d][j]
__device__ float g_ps[ISPLIT*NPIX];    // partial s [split][j]

__device__ __forceinline__ uint32_t smem_u32(const void* p) {
    uint32_t a;
    asm("{ .reg .u64 t; cvta.to.shared.u64 t, %1; cvt.u32.u64 %0, t; }" : "=r"(a) : "l"(p));
    return a;
}

#define LDSM4(r0,r1,r2,r3,addr) \
    asm volatile("ldmatrix.sync.aligned.m8n8.x4.shared.b16 {%0,%1,%2,%3}, [%4];" \
        : "=r"(r0),"=r"(r1),"=r"(r2),"=r"(r3) : "r"(addr))

#define MMA16816(C, A, b0, b1) \
    asm volatile("mma.sync.aligned.m16n8k16.row.col.f32.f16.f16.f32 " \
        "{%0,%1,%2,%3}, {%4,%5,%6,%7}, {%8,%9}, {%0,%1,%2,%3};" \
        : "+f"((C)[0]), "+f"((C)[1]), "+f"((C)[2]), "+f"((C)[3]) \
        : "r"((A)[0]), "r"((A)[1]), "r"((A)[2]), "r"((A)[3]), "r"(b0), "r"(b1))

__device__ __forceinline__ void cp16(uint32_t dst, const void* src) {
    asm volatile("cp.async.ca.shared.global [%0], [%1], 16;"
        :: "r"(dst), "l"(__cvta_generic_to_global(src)) : "memory");
}
__device__ __forceinline__ uint32_t pkh2(float lo, float hi) {
    uint32_t r; asm("cvt.rn.f16x2.f32 %0, %1, %2;" : "=r"(r) : "f"(hi), "f"(lo)); return r;
}
__device__ __forceinline__ uint32_t ex2h2(uint32_t x) {
    uint32_t r; asm("ex2.approx.f16x2 %0, %1;" : "=r"(r) : "r"(x)); return r;
}

// smem layout:
//   sXi: 2 bufs x (64 rows x 80B)   [i][d]        -> 10240 B
//   sXd: 2 bufs x (40 rows x 144B)  [d(+ones)][i] -> 11520 B
#define SXI_STRIDE 80
#define SXD_STRIDE 144
#define SXI_BUF (TI*SXI_STRIDE)      // 5120
#define SXD_BUF (40*SXD_STRIDE)      // 5760
#define SMEM_BYTES (2*SXI_BUF + 2*SXD_BUF)

__global__ void __launch_bounds__(256, 2) ms_main()
{
    __shared__ __align__(128) unsigned char smem_buf[SMEM_BYTES];
    const uint32_t sXi = smem_u32(smem_buf);
    const uint32_t sXd = sXi + 2 * SXI_BUF;

    const int tid = threadIdx.x;
    const int w = tid >> 5;
    const int l = tid & 31;
    const int jb = blockIdx.x * JT;
    const int split = blockIdx.y;
    const int i0b = split * IRANGE;

    // extra Xd rows: row 32 = ones (s column), rows 33..39 = zeros
    for (int idx = tid; idx < 512; idx += 256) {
        int b = idx >> 8, rem = idx & 255;
        int r = rem >> 5, cw = rem & 31;
        uint32_t v = (r == 0) ? 0x3C003C00u : 0u;
        *(uint32_t*)(smem_buf + 2 * SXI_BUF + b * SXD_BUF + (32 + r) * SXD_STRIDE + cw * 4) = v;
    }

    // A1 fragments for two j16 blocks: rows jb + w*32 (+16)
    const uint32_t* xq32 = (const uint32_t*)g_xq;
    uint32_t a1f[2][2][4];
#pragma unroll
    for (int jblk = 0; jblk < 2; jblk++) {
        const int row0 = jb + w * 32 + jblk * 16 + (l >> 2);
#pragma unroll
        for (int ks = 0; ks < 2; ks++) {
            a1f[jblk][ks][0] = xq32[row0 * 16 + ks * 8 + (l & 3)];
            a1f[jblk][ks][1] = xq32[(row0 + 8) * 16 + ks * 8 + (l & 3)];
            a1f[jblk][ks][2] = xq32[row0 * 16 + ks * 8 + 4 + (l & 3)];
            a1f[jblk][ks][3] = xq32[(row0 + 8) * 16 + ks * 8 + 4 + (l & 3)];
        }
    }

    float vf[2][5][4];
#pragma unroll
    for (int jblk = 0; jblk < 2; jblk++)
#pragma unroll
        for (int n = 0; n < 5; n++)
#pragma unroll
            for (int q = 0; q < 4; q++) vf[jblk][n][q] = 0.0f;

    const char* gxp = (const char*)g_xp;
    const char* gxa = (const char*)g_xa;

    const int xi_r = tid >> 2, xi_c = tid & 3;   // 64 rows x 4 x 16B
    const int xd_r = tid >> 3, xd_c = tid & 7;   // 32 rows x 8 x 16B

#define ISSUE(c) do { \
        int i0_ = i0b + (c) * TI; int b_ = (c) & 1; \
        cp16(sXi + b_ * SXI_BUF + xi_r * SXI_STRIDE + xi_c * 16, \
             gxp + (size_t)(i0_ + xi_r) * 64 + xi_c * 16); \
        cp16(sXd + b_ * SXD_BUF + xd_r * SXD_STRIDE + xd_c * 16, \
             gxa + ((size_t)xd_r * NPIX + i0_) * 2 + xd_c * 16); \
        asm volatile("cp.async.commit_group;" ::: "memory"); \
    } while (0)

    ISSUE(0);

    for (int c = 0; c < NCH; c++) {
        if (c + 1 < NCH) {
            ISSUE(c + 1);
            asm volatile("cp.async.wait_group 1;" ::: "memory");
        } else {
            asm volatile("cp.async.wait_group 0;" ::: "memory");
        }
        __syncthreads();

        const uint32_t pXi = sXi + (c & 1) * SXI_BUF;
        const uint32_t pXd = sXd + (c & 1) * SXD_BUF;

        // ---- MMA1 + exp: B fragments shared across the two j16 blocks ----
        uint32_t a2f[2][4][4];
#pragma unroll
        for (int n = 0; n < 8; n++) {
            uint32_t q0, q1, q2, q3;
            uint32_t addr = pXi + (n * 8 + (l & 7)) * SXI_STRIDE + (l >> 3) * 16;
            LDSM4(q0, q1, q2, q3, addr);
            int kk = n >> 1;
#pragma unroll
            for (int jblk = 0; jblk < 2; jblk++) {
                float C[4];
                C[0] = 0.f; C[1] = 0.f; C[2] = 0.f; C[3] = 0.f;
                MMA16816(C, a1f[jblk][0], q0, q1);
                MMA16816(C, a1f[jblk][1], q2, q3);
                uint32_t e01 = ex2h2(pkh2(C[0], C[1]));
                uint32_t e23 = ex2h2(pkh2(C[2], C[3]));
                if ((n & 1) == 0) { a2f[jblk][kk][0] = e01; a2f[jblk][kk][1] = e23; }
                else             { a2f[jblk][kk][2] = e01; a2f[jblk][kk][3] = e23; }
            }
        }

        // ---- MMA2: V[j, d(40)] += P * Xd ; B shared across j-blocks ----
#pragma unroll
        for (int nd = 0; nd < 5; nd++) {
#pragma unroll
            for (int p = 0; p < 2; p++) {
                uint32_t q0, q1, q2, q3;
                uint32_t addr = pXd + (nd * 8 + (l & 7)) * SXD_STRIDE + p * 64 + (l >> 3) * 16;
                LDSM4(q0, q1, q2, q3, addr);
#pragma unroll
                for (int jblk = 0; jblk < 2; jblk++) {
                    MMA16816(vf[jblk][nd], a2f[jblk][2 * p], q0, q1);
                    MMA16816(vf[jblk][nd], a2f[jblk][2 * p + 1], q2, q3);
                }
            }
        }
        __syncthreads();
    }

    // ---- s from ones-column (col 32 => nd=4, (l&3)==0, q in {0,2}) ----
#pragma unroll
    for (int jblk = 0; jblk < 2; jblk++) {
        if ((l & 3) == 0) {
            int j0 = jb + w * 32 + jblk * 16 + (l >> 2);
            g_ps[split * NPIX + j0] = vf[jblk][4][0];
            g_ps[split * NPIX + j0 + 8] = vf[jblk][4][2];
        }
    }

    // ---- V writeback ----
#pragma unroll
    for (int jblk = 0; jblk < 2; jblk++)
#pragma unroll
        for (int nd = 0; nd < 4; nd++)
#pragma unroll
            for (int q = 0; q < 4; q++) {
                int d = nd * 8 + (l & 3) * 2 + (q & 1);
                int j = jb + w * 32 + jblk * 16 + (l >> 2) + ((q >= 2) ? 8 : 0);
                g_pv[(split * DIMK + d) * NPIX + j] = vf[jblk][nd][q];
            }
}

// fp32 input -> the three f16 layouts
__global__ void ms_prep(const float* __restrict__ x)
{
    int j = blockIdx.x * 256 + threadIdx.x;
    float v[DIMK];
#pragma unroll
    for (int d = 0; d < DIMK; d++) {
        v[d] = x[d * NPIX + j];
        g_xa[d * NPIX + j] = __float2half_rn(v[d]);
    }
    uint32_t* xp32 = (uint32_t*)g_xp;
    uint32_t* xq32 = (uint32_t*)g_xq;
#pragma unroll
    for (int d = 0; d < DIMK; d += 2) {
        xp32[j * 16 + d / 2] = pkh2(v[d], v[d + 1]);
        xq32[j * 16 + d / 2] = pkh2(v[d] * SCALE, v[d + 1] * SCALE);
    }
}

// combine partials, apply update, refresh layouts, write outputs
__global__ void ms_reduce(const float* __restrict__ xext, int use_ext,
                          float* __restrict__ out, int stack_off, int final_off)
{
    int j = blockIdx.x * 256 + threadIdx.x;
    float s = 0.0f;
#pragma unroll
    for (int ib = 0; ib < ISPLIT; ib++) s += g_ps[ib * NPIX + j];
    float inv = 0.5f / s;
    float v[DIMK];
#pragma unroll
    for (int d = 0; d < DIMK; d++) {
        float pv = 0.0f;
#pragma unroll
        for (int ib = 0; ib < ISPLIT; ib++) pv += g_pv[(ib * DIMK + d) * NPIX + j];
        float xo = use_ext ? xext[d * NPIX + j] : g_xf[d * NPIX + j];
        float val = pv * inv + 0.5f * xo;
        v[d] = val;
        out[stack_off + d * NPIX + j] = val;
        if (final_off >= 0) out[final_off + d * NPIX + j] = val;
        g_xf[d * NPIX + j] = val;
        g_xa[d * NPIX + j] = __float2half_rn(val);
    }
    uint32_t* xp32 = (uint32_t*)g_xp;
    uint32_t* xq32 = (uint32_t*)g_xq;
#pragma unroll
    for (int d = 0; d < DIMK; d += 2) {
        xp32[j * 16 + d / 2] = pkh2(v[d], v[d + 1]);
        xq32[j * 16 + d / 2] = pkh2(v[d] * SCALE, v[d + 1] * SCALE);
    }
}

extern "C" void kernel_launch(void* const* d_in, const int* in_sizes, int n_in,
                              void* d_out, int out_size)
{
    const float* x = (const float*)d_in[0];
    float* out = (float*)d_out;

    dim3 grid_main(NPIX / JT, ISPLIT);   // (36, 8) = 288 CTAs, 2 per SM

    ms_prep<<<NPIX / 256, 256>>>(x);
    for (int it = 0; it < 3; it++) {
        ms_main<<<grid_main, 256>>>();
        ms_reduce<<<NPIX / 256, 256>>>(x, it == 0 ? 1 : 0, out,
                                       FELEMS * (1 + it), it == 2 ? 0 : -1);
    }
}

// round 8
// speedup vs baseline: 6.9833x; 1.3490x over previous
#include <cuda_runtime.h>
#include <cuda_fp16.h>
#include <stdint.h>

#define NPIX 9216
#define DIMK 32
#define FELEMS (DIMK*NPIX)
#define JT 256
#define TI 64
#define ISPLIT 8
#define IRANGE (NPIX/ISPLIT)   // 1152
#define NCH (IRANGE/TI)        // 18
#define NCTA 288
#define SCALE 4.328085122666891f   // 3 * log2(e)

// device scratch (no allocations allowed)
__device__ __half g_xq[NPIX*DIMK];   // [pixel][d], scaled by 3*log2e (A1 operand)
__device__ __half g_xp[NPIX*DIMK];   // [pixel][d], unscaled (B1 operand)
__device__ __half g_xa[DIMK*NPIX];   // [d][pixel], unscaled (B2 operand)
__device__ float g_xf[FELEMS];       // current x fp32, d-major
__device__ float g_pv[ISPLIT*FELEMS];  // partial v [split][d][j]
__device__ float g_ps[ISPLIT*NPIX];    // partial s [split][j]

// grid barrier state (self-resetting across launches)
__device__ unsigned g_cnt = 0;
__device__ volatile unsigned g_gen = 0;

__device__ __forceinline__ void gsync() {
    __syncthreads();
    if (threadIdx.x == 0) {
        unsigned my = g_gen;
        __threadfence();
        if (atomicAdd(&g_cnt, 1) == NCTA - 1) {
            g_cnt = 0;
            __threadfence();
            g_gen = my + 1;
        } else {
            while (g_gen == my) {}
            __threadfence();
        }
    }
    __syncthreads();
}

__device__ __forceinline__ uint32_t smem_u32(const void* p) {
    uint32_t a;
    asm("{ .reg .u64 t; cvta.to.shared.u64 t, %1; cvt.u32.u64 %0, t; }" : "=r"(a) : "l"(p));
    return a;
}

#define LDSM4(r0,r1,r2,r3,addr) \
    asm volatile("ldmatrix.sync.aligned.m8n8.x4.shared.b16 {%0,%1,%2,%3}, [%4];" \
        : "=r"(r0),"=r"(r1),"=r"(r2),"=r"(r3) : "r"(addr))

#define MMA16816(C, A, b0, b1) \
    asm volatile("mma.sync.aligned.m16n8k16.row.col.f32.f16.f16.f32 " \
        "{%0,%1,%2,%3}, {%4,%5,%6,%7}, {%8,%9}, {%0,%1,%2,%3};" \
        : "+f"((C)[0]), "+f"((C)[1]), "+f"((C)[2]), "+f"((C)[3]) \
        : "r"((A)[0]), "r"((A)[1]), "r"((A)[2]), "r"((A)[3]), "r"(b0), "r"(b1))

// L1-bypassing tile copy (cross-CTA data changes between iterations)
__device__ __forceinline__ void cp16cg(uint32_t dst, const void* src) {
    asm volatile("cp.async.cg.shared.global [%0], [%1], 16;"
        :: "r"(dst), "l"(__cvta_generic_to_global(src)) : "memory");
}
__device__ __forceinline__ uint32_t pkh2(float lo, float hi) {
    uint32_t r; asm("cvt.rn.f16x2.f32 %0, %1, %2;" : "=r"(r) : "f"(hi), "f"(lo)); return r;
}
__device__ __forceinline__ uint32_t ex2h2(uint32_t x) {
    uint32_t r; asm("ex2.approx.f16x2 %0, %1;" : "=r"(r) : "r"(x)); return r;
}

// smem: 3 bufs of (sXi 64x80B) + 3 bufs of (sXd 40x144B)
#define SXI_STRIDE 80
#define SXD_STRIDE 144
#define SXI_BUF (TI*SXI_STRIDE)      // 5120
#define SXD_BUF (40*SXD_STRIDE)      // 5760
#define SMEM_BYTES (3*SXI_BUF + 3*SXD_BUF)   // 32640

struct SmemT { unsigned char buf[SMEM_BYTES]; };

__device__ __forceinline__ void main_phase(SmemT* sm, int jb, int split)
{
    const uint32_t sXi = smem_u32(sm->buf);
    const uint32_t sXd = sXi + 3 * SXI_BUF;
    const int tid = threadIdx.x;
    const int w = tid >> 5;
    const int l = tid & 31;
    const int i0b = split * IRANGE;

    // A1 fragments (g_xq mutated by reduce phase -> L2 loads)
    const uint32_t* xq32 = (const uint32_t*)g_xq;
    uint32_t a1f[2][2][4];
#pragma unroll
    for (int jblk = 0; jblk < 2; jblk++) {
        const int row0 = jb + w * 32 + jblk * 16 + (l >> 2);
#pragma unroll
        for (int ks = 0; ks < 2; ks++) {
            a1f[jblk][ks][0] = __ldcg(&xq32[row0 * 16 + ks * 8 + (l & 3)]);
            a1f[jblk][ks][1] = __ldcg(&xq32[(row0 + 8) * 16 + ks * 8 + (l & 3)]);
            a1f[jblk][ks][2] = __ldcg(&xq32[row0 * 16 + ks * 8 + 4 + (l & 3)]);
            a1f[jblk][ks][3] = __ldcg(&xq32[(row0 + 8) * 16 + ks * 8 + 4 + (l & 3)]);
        }
    }

    float vf[2][5][4];
#pragma unroll
    for (int jblk = 0; jblk < 2; jblk++)
#pragma unroll
        for (int n = 0; n < 5; n++)
#pragma unroll
            for (int q = 0; q < 4; q++) vf[jblk][n][q] = 0.0f;

    const char* gxp = (const char*)g_xp;
    const char* gxa = (const char*)g_xa;
    const int xi_r = tid >> 2, xi_c = tid & 3;
    const int xd_r = tid >> 3, xd_c = tid & 7;

#define ISSUE(c) do { \
        int i0_ = i0b + (c) * TI; int b_ = (c) % 3; \
        cp16cg(sXi + b_ * SXI_BUF + xi_r * SXI_STRIDE + xi_c * 16, \
               gxp + (size_t)(i0_ + xi_r) * 64 + xi_c * 16); \
        cp16cg(sXd + b_ * SXD_BUF + xd_r * SXD_STRIDE + xd_c * 16, \
               gxa + ((size_t)xd_r * NPIX + i0_) * 2 + xd_c * 16); \
        asm volatile("cp.async.commit_group;" ::: "memory"); \
    } while (0)

    ISSUE(0);

    for (int c = 0; c < NCH; c++) {
        if (c + 1 < NCH) {
            ISSUE(c + 1);
            asm volatile("cp.async.wait_group 1;" ::: "memory");
        } else {
            asm volatile("cp.async.wait_group 0;" ::: "memory");
        }
        __syncthreads();   // only barrier per chunk (triple-buffered)

        const uint32_t pXi = sXi + (c % 3) * SXI_BUF;
        const uint32_t pXd = sXd + (c % 3) * SXD_BUF;

        // ---- MMA1 + exp, B shared across the two j16 blocks ----
        uint32_t a2f[2][4][4];
#pragma unroll
        for (int n = 0; n < 8; n++) {
            uint32_t q0, q1, q2, q3;
            uint32_t addr = pXi + (n * 8 + (l & 7)) * SXI_STRIDE + (l >> 3) * 16;
            LDSM4(q0, q1, q2, q3, addr);
            int kk = n >> 1;
#pragma unroll
            for (int jblk = 0; jblk < 2; jblk++) {
                float C[4];
                C[0] = 0.f; C[1] = 0.f; C[2] = 0.f; C[3] = 0.f;
                MMA16816(C, a1f[jblk][0], q0, q1);
                MMA16816(C, a1f[jblk][1], q2, q3);
                uint32_t e01 = ex2h2(pkh2(C[0], C[1]));
                uint32_t e23 = ex2h2(pkh2(C[2], C[3]));
                if ((n & 1) == 0) { a2f[jblk][kk][0] = e01; a2f[jblk][kk][1] = e23; }
                else             { a2f[jblk][kk][2] = e01; a2f[jblk][kk][3] = e23; }
            }
        }

        // ---- MMA2: V[j, d(40)] += P * Xd (col 32 = ones -> rowsum) ----
#pragma unroll
        for (int nd = 0; nd < 5; nd++) {
#pragma unroll
            for (int p = 0; p < 2; p++) {
                uint32_t q0, q1, q2, q3;
                uint32_t addr = pXd + (nd * 8 + (l & 7)) * SXD_STRIDE + p * 64 + (l >> 3) * 16;
                LDSM4(q0, q1, q2, q3, addr);
#pragma unroll
                for (int jblk = 0; jblk < 2; jblk++) {
                    MMA16816(vf[jblk][nd], a2f[jblk][2 * p], q0, q1);
                    MMA16816(vf[jblk][nd], a2f[jblk][2 * p + 1], q2, q3);
                }
            }
        }
    }
#undef ISSUE

    // ---- s from ones-column ----
#pragma unroll
    for (int jblk = 0; jblk < 2; jblk++) {
        if ((l & 3) == 0) {
            int j0 = jb + w * 32 + jblk * 16 + (l >> 2);
            g_ps[split * NPIX + j0] = vf[jblk][4][0];
            g_ps[split * NPIX + j0 + 8] = vf[jblk][4][2];
        }
    }
    // ---- V writeback ----
#pragma unroll
    for (int jblk = 0; jblk < 2; jblk++)
#pragma unroll
        for (int nd = 0; nd < 4; nd++)
#pragma unroll
            for (int q = 0; q < 4; q++) {
                int d = nd * 8 + (l & 3) * 2 + (q & 1);
                int j = jb + w * 32 + jblk * 16 + (l >> 2) + ((q >= 2) ? 8 : 0);
                g_pv[(split * DIMK + d) * NPIX + j] = vf[jblk][nd][q];
            }
}

// it == -1: prep (convert input). it >= 0: combine partials + update + outputs.
// Same j-partition per CTA in all calls -> own-L1 lines stay coherent.
__device__ __forceinline__ void cvt_phase(int it, const float* __restrict__ x,
                                          float* __restrict__ out, int bid)
{
    const int tid = threadIdx.x;
    const int j = bid * 32 + (tid & 31);
    const int dg = tid >> 5;            // 0..7 -> d in [dg*4, dg*4+4)
    float inv = 0.0f;
    if (it >= 0) {
        float s = 0.0f;
#pragma unroll
        for (int ib = 0; ib < ISPLIT; ib++) s += __ldcg(&g_ps[ib * NPIX + j]);
        inv = 0.5f / s;
    }
    float v[4];
#pragma unroll
    for (int q = 0; q < 4; q++) {
        int d = dg * 4 + q;
        float xo = (it <= 0) ? x[d * NPIX + j] : g_xf[d * NPIX + j];
        if (it < 0) {
            v[q] = xo;
        } else {
            float pv = 0.0f;
#pragma unroll
            for (int ib = 0; ib < ISPLIT; ib++)
                pv += __ldcg(&g_pv[(ib * DIMK + d) * NPIX + j]);
            float val = pv * inv + 0.5f * xo;
            v[q] = val;
            out[(1 + it) * FELEMS + d * NPIX + j] = val;
            if (it == 2) out[d * NPIX + j] = val;
            if (it < 2) g_xf[d * NPIX + j] = val;
        }
        if (it < 2) g_xa[d * NPIX + j] = __float2half_rn(v[q]);
    }
    if (it < 2) {
        uint32_t* xp32 = (uint32_t*)g_xp;
        uint32_t* xq32 = (uint32_t*)g_xq;
#pragma unroll
        for (int q = 0; q < 4; q += 2) {
            int d = dg * 4 + q;
            xp32[j * 16 + d / 2] = pkh2(v[q], v[q + 1]);
            xq32[j * 16 + d / 2] = pkh2(v[q] * SCALE, v[q + 1] * SCALE);
        }
    }
}

__global__ void __launch_bounds__(256, 2) ms_all(const float* __restrict__ x,
                                                float* __restrict__ out)
{
    __shared__ __align__(128) SmemT sm;
    const int bid = blockIdx.x;
    const int tid = threadIdx.x;
    const int jb = (bid % 36) * JT;
    const int split = bid / 36;

    // init static sXd rows 32..39 (ones row + zero pad) in all 3 buffers
    for (int idx = tid; idx < 3 * 8 * 32; idx += 256) {
        int b = idx >> 8, rem = idx & 255;
        int r = rem >> 5, cw = rem & 31;
        uint32_t v = (r == 0) ? 0x3C003C00u : 0u;
        *(uint32_t*)(sm.buf + 3 * SXI_BUF + b * SXD_BUF + (32 + r) * SXD_STRIDE + cw * 4) = v;
    }

    cvt_phase(-1, x, out, bid);   // prep
    gsync();
    for (int it = 0; it < 3; it++) {
        main_phase(&sm, jb, split);
        gsync();
        cvt_phase(it, x, out, bid);
        if (it < 2) gsync();
    }
}

extern "C" void kernel_launch(void* const* d_in, const int* in_sizes, int n_in,
                              void* d_out, int out_size)
{
    const float* x = (const float*)d_in[0];
    float* out = (float*)d_out;
    ms_all<<<NCTA, 256>>>(x, out);
}